// round 1
// baseline (speedup 1.0000x reference)
#include <cuda_runtime.h>
#include <cuda_bf16.h>
#include <cstdint>

// Problem constants
#define N_B    32
#define C_IN   256
#define L_LEN  4096
#define C_OUT  256
#define KW     9
#define GROUPS 4
#define CPG    64     // C_in per group
#define OPG    64     // C_out per group
#define C_DIM  128
#define PAD    4

// Tiling
#define L_TILE   128
#define IC_CHUNK 16
#define XS_W     (L_TILE + KW - 1)   // 136

typedef unsigned long long ull_t;

// Scratch for context term (32*256 floats) — static device global, no allocation.
__device__ float g_ctx[N_B * C_OUT];

__device__ __forceinline__ ull_t pack2(float lo, float hi) {
    ull_t r;
    asm("mov.b64 %0, {%1, %2};" : "=l"(r) : "f"(lo), "f"(hi));
    return r;
}
__device__ __forceinline__ void unpack2(ull_t v, float& lo, float& hi) {
    asm("mov.b64 {%0, %1}, %2;" : "=f"(lo), "=f"(hi) : "l"(v));
}
// Packed fp32x2 FMA (Blackwell FFMA2 — PTX-only path)
__device__ __forceinline__ ull_t fma2(ull_t a, ull_t b, ull_t c) {
    ull_t d;
    asm("fma.rn.f32x2 %0, %1, %2, %3;" : "=l"(d) : "l"(a), "l"(b), "l"(c));
    return d;
}

// ---------------------------------------------------------------------------
// Kernel 1: context term  g_ctx[n][oc] = sum_d c[n][d] * c_weight[oc][d]
// Tiny (1M FMA) — simplicity over efficiency.
// ---------------------------------------------------------------------------
__global__ void ctx_kernel(const float* __restrict__ c,
                           const float* __restrict__ cw) {
    int n  = blockIdx.x;
    int oc = threadIdx.x;
    const float* crow  = c  + (size_t)n  * C_DIM;
    const float* cwrow = cw + (size_t)oc * C_DIM;
    float s = 0.f;
#pragma unroll 8
    for (int d = 0; d < C_DIM; d++) s += crow[d] * cwrow[d];
    g_ctx[n * C_OUT + oc] = s;
}

// ---------------------------------------------------------------------------
// Kernel 2: grouped conv1d, fp32, f32x2-packed over output-channel pairs.
// Block = (l_tile, group, n). 256 threads.
// Thread tile: 4 oc (2 pairs) x 8 l, register accumulators (fp32x2).
// ---------------------------------------------------------------------------
__global__ void __launch_bounds__(256, 2)
conv_kernel(const float* __restrict__ x,
            const float* __restrict__ w,
            const float* __restrict__ bias,
            float* __restrict__ out) {
    __shared__ float xs[IC_CHUNK][XS_W];          // 8,704 B
    __shared__ float ws[IC_CHUNK][KW][OPG];       // 36,864 B  (total 45,568 B)

    const int lt = blockIdx.x;       // 0..31
    const int g  = blockIdx.y;       // 0..3
    const int n  = blockIdx.z;       // 0..31
    const int l0 = lt * L_TILE;
    const int t  = threadIdx.x;

    const int oc0 = (t & 15) * 4;    // 0,4,...,60
    const int lb  = (t >> 4) * 8;    // 0,8,...,120

    ull_t acc[2][8];
#pragma unroll
    for (int p = 0; p < 2; p++)
#pragma unroll
        for (int l = 0; l < 8; l++) acc[p][l] = 0ull;

    for (int cc = 0; cc < CPG; cc += IC_CHUNK) {
        // ---- load x chunk (zero-padded at sequence boundaries) ----
        for (int idx = t; idx < IC_CHUNK * XS_W; idx += 256) {
            int ic = idx / XS_W;
            int j  = idx - ic * XS_W;
            int gl = l0 - PAD + j;
            float v = 0.f;
            if (gl >= 0 && gl < L_LEN)
                v = x[((size_t)(n * C_IN + g * CPG + cc + ic)) * L_LEN + gl];
            xs[ic][j] = v;
        }
        // ---- load weight chunk, transposed to [ic][k][oc] ----
        for (int idx = t; idx < IC_CHUNK * KW * OPG; idx += 256) {
            int oc  = idx & 63;
            int rem = idx >> 6;
            int k   = rem % KW;
            int ic  = rem / KW;
            ws[ic][k][oc] =
                w[(size_t)(g * OPG + oc) * (CPG * KW) + (cc + ic) * KW + k];
        }
        __syncthreads();

#pragma unroll 1
        for (int ic = 0; ic < IC_CHUNK; ic++) {
            // 16 x-values, broadcast-packed once; reused by 9 taps x 2 pairs.
            ull_t xb[16];
            const float4* xrow = (const float4*)&xs[ic][lb];
#pragma unroll
            for (int q = 0; q < 4; q++) {
                float4 v = xrow[q];
                xb[4 * q + 0] = pack2(v.x, v.x);
                xb[4 * q + 1] = pack2(v.y, v.y);
                xb[4 * q + 2] = pack2(v.z, v.z);
                xb[4 * q + 3] = pack2(v.w, v.w);
            }
#pragma unroll
            for (int k = 0; k < KW; k++) {
                ull_t w0 = *(const ull_t*)&ws[ic][k][oc0];      // {w[oc0],w[oc0+1]}
                ull_t w1 = *(const ull_t*)&ws[ic][k][oc0 + 2];  // {w[oc0+2],w[oc0+3]}
#pragma unroll
                for (int l = 0; l < 8; l++) {
                    acc[0][l] = fma2(w0, xb[l + k], acc[0][l]);
                    acc[1][l] = fma2(w1, xb[l + k], acc[1][l]);
                }
            }
        }
        __syncthreads();
    }

    // ---- epilogue: add context + bias, store ----
#pragma unroll
    for (int p = 0; p < 2; p++) {
        int ocA = g * OPG + oc0 + 2 * p;
        int ocB = ocA + 1;
        float addA = g_ctx[n * C_OUT + ocA] + bias[ocA];
        float addB = g_ctx[n * C_OUT + ocB] + bias[ocB];
        float* rowA = out + ((size_t)n * C_OUT + ocA) * L_LEN + l0 + lb;
        float* rowB = out + ((size_t)n * C_OUT + ocB) * L_LEN + l0 + lb;
        float bufA[8], bufB[8];
#pragma unroll
        for (int l = 0; l < 8; l++) {
            float lo, hi;
            unpack2(acc[p][l], lo, hi);
            bufA[l] = lo + addA;
            bufB[l] = hi + addB;
        }
        ((float4*)rowA)[0] = make_float4(bufA[0], bufA[1], bufA[2], bufA[3]);
        ((float4*)rowA)[1] = make_float4(bufA[4], bufA[5], bufA[6], bufA[7]);
        ((float4*)rowB)[0] = make_float4(bufB[0], bufB[1], bufB[2], bufB[3]);
        ((float4*)rowB)[1] = make_float4(bufB[4], bufB[5], bufB[6], bufB[7]);
    }
}

extern "C" void kernel_launch(void* const* d_in, const int* in_sizes, int n_in,
                              void* d_out, int out_size) {
    const float* x    = (const float*)d_in[0];  // (32, 256, 4096)
    const float* c    = (const float*)d_in[1];  // (32, 128)
    const float* w    = (const float*)d_in[2];  // (256, 64, 9)
    const float* cw   = (const float*)d_in[3];  // (256, 128)
    const float* bias = (const float*)d_in[4];  // (256,)
    float* out = (float*)d_out;                 // (32, 256, 4096)

    ctx_kernel<<<N_B, C_OUT>>>(c, cw);

    dim3 grid(L_LEN / L_TILE, GROUPS, N_B);     // (32, 4, 32)
    conv_kernel<<<grid, 256>>>(x, w, bias, out);
}

// round 3
// speedup vs baseline: 4.0373x; 4.0373x over previous
#include <cuda_runtime.h>
#include <cstdint>

// ---------------- problem constants ----------------
#define N_B    32
#define C_IN   256
#define L_LEN  4096
#define C_OUT  256
#define KW     9
#define GROUPS 4
#define CPG    64
#define OPG    64
#define C_DIM  128
#define PAD    4

#define L_TILE 256
#define NTHR   256
#define XS_STRIDE 268                       // words; %32==12, 16B-aligned rows

// smem layout (bytes)
#define SM_XS   0                           // 64 x 268 u32 = 68,608 (also epilogue buf)
#define SM_B0   (64 * XS_STRIDE * 4)        // 16 KB fragment-ordered B tile
#define SM_B1   (SM_B0 + 16384)
#define SM_TOTAL (SM_B1 + 16384)            // 101,376 B

// ---------------- device scratch ----------------
__device__ float g_ctx[N_B * C_OUT];
__device__ unsigned int g_wt[GROUPS * KW * 4096];   // fragment-ordered tf32 B tiles

__device__ __forceinline__ uint32_t tf32rn(float f) {
    uint32_t r;
    asm("cvt.rna.tf32.f32 %0, %1;" : "=r"(r) : "f"(f));
    return r;
}

__device__ __forceinline__ void mma_tf32(float* d, const uint32_t* a, uint32_t b0, uint32_t b1) {
    asm volatile(
        "mma.sync.aligned.m16n8k8.row.col.f32.tf32.tf32.f32 "
        "{%0,%1,%2,%3}, {%4,%5,%6,%7}, {%8,%9}, {%0,%1,%2,%3};"
        : "+f"(d[0]), "+f"(d[1]), "+f"(d[2]), "+f"(d[3])
        : "r"(a[0]), "r"(a[1]), "r"(a[2]), "r"(a[3]), "r"(b0), "r"(b1));
}

// ---------------------------------------------------------------------------
// Kernel 1: context term  g_ctx[n][oc] = c[n] . c_weight[oc]   (fp32 exact)
// ---------------------------------------------------------------------------
__global__ void ctx_kernel(const float* __restrict__ c, const float* __restrict__ cw) {
    int n = blockIdx.x, oc = threadIdx.x;
    const float* cr = c + (size_t)n * C_DIM;
    const float* wr = cw + (size_t)oc * C_DIM;
    float s = 0.f;
#pragma unroll 8
    for (int d = 0; d < C_DIM; d++) s += cr[d] * wr[d];
    g_ctx[n * C_OUT + oc] = s;
}

// ---------------------------------------------------------------------------
// Kernel 2: weights -> tf32, exact mma.sync B-fragment order.
// Per (g,k): 4096 u32. idx = ((s*4+q)*32+lane)*4 + r
//   f = 2q + (r>>1); oc = 8f + (lane>>2); ic = 8s + (lane&3) + 4*(r&1)
// ---------------------------------------------------------------------------
__global__ void wt_kernel(const float* __restrict__ w) {
    int g = blockIdx.x, k = blockIdx.y;
    unsigned int* dst = g_wt + (size_t)(g * KW + k) * 4096;
    for (int idx = threadIdx.x; idx < 4096; idx += NTHR) {
        int r    = idx & 3;
        int lane = (idx >> 2) & 31;
        int q    = (idx >> 7) & 3;
        int s    = idx >> 9;
        int f    = 2 * q + (r >> 1);
        int oc   = 8 * f + (lane >> 2);
        int ic   = 8 * s + (lane & 3) + 4 * (r & 1);
        dst[idx] = tf32rn(w[(size_t)(g * OPG + oc) * (CPG * KW) + ic * KW + k]);
    }
}

// ---------------------------------------------------------------------------
// Kernel 3: grouped conv as implicit GEMM on mma.sync (tf32, fp32 accum).
// Block (lt, g, n): 256 l x 64 oc. 8 warps: warp = 32 l x 64 oc.
// ---------------------------------------------------------------------------
__global__ void __launch_bounds__(NTHR, 2)
conv_kernel(const float* __restrict__ x, const float* __restrict__ bias,
            float* __restrict__ out) {
    extern __shared__ char smem[];
    uint32_t* xs = (uint32_t*)(smem + SM_XS);

    const int tid = threadIdx.x;
    const int wid = tid >> 5, lane = tid & 31;
    const int lt = blockIdx.x, g = blockIdx.y, n = blockIdx.z;
    const int l0 = lt * L_TILE;

    // ---- stage x tile (tf32-rounded): xs[ic][j] = x[n][g*64+ic][l0-PAD+j] ----
    {
        const float* xb = x + ((size_t)(n * C_IN + g * CPG)) * L_LEN;
        for (int idx = tid; idx < CPG * (L_TILE + 8); idx += NTHR) {
            int ic = idx / (L_TILE + 8);
            int j  = idx - ic * (L_TILE + 8);
            int gl = l0 - PAD + j;
            float v = (gl >= 0 && gl < L_LEN) ? xb[(size_t)ic * L_LEN + gl] : 0.f;
            xs[ic * XS_STRIDE + j] = tf32rn(v);
        }
    }
    // ---- prologue: B_0 into buffer 0 ----
    {
        const float4* src = (const float4*)(g_wt + (size_t)(g * KW) * 4096);
        float4* dst = (float4*)(smem + SM_B0);
#pragma unroll
        for (int i = 0; i < 4; i++) dst[tid + i * NTHR] = src[tid + i * NTHR];
    }
    __syncthreads();

    // ---- accumulators: warp tile 32 l x 64 oc = 2 (mi) x 8 (f) frags ----
    float d[2][8][4];
#pragma unroll
    for (int mi = 0; mi < 2; mi++)
#pragma unroll
        for (int f = 0; f < 8; f++)
#pragma unroll
            for (int r = 0; r < 4; r++) d[mi][f][r] = 0.f;

    const int ml = wid * 32;
    const int ar = lane >> 2;      // a-frag row
    const int ac = lane & 3;       // a-frag col (ic offset)

#pragma unroll 1
    for (int k = 0; k < KW; k++) {
        const uint32_t* bb = (const uint32_t*)(smem + ((k & 1) ? SM_B1 : SM_B0));

        // prefetch next tap's B into registers
        float4 pf0, pf1, pf2, pf3;
        if (k < KW - 1) {
            const float4* src = (const float4*)(g_wt + (size_t)(g * KW + k + 1) * 4096);
            pf0 = src[tid]; pf1 = src[tid + NTHR];
            pf2 = src[tid + 2 * NTHR]; pf3 = src[tid + 3 * NTHR];
        }

#pragma unroll
        for (int s = 0; s < 8; s++) {
            // A fragments from shifted x window
            uint32_t a[2][4];
            {
                const uint32_t* r0 = xs + (s * 8 + ac) * XS_STRIDE + (ml + ar + k);
                const uint32_t* r4 = r0 + 4 * XS_STRIDE;
#pragma unroll
                for (int mi = 0; mi < 2; mi++) {
                    a[mi][0] = r0[mi * 16];
                    a[mi][1] = r0[mi * 16 + 8];
                    a[mi][2] = r4[mi * 16];
                    a[mi][3] = r4[mi * 16 + 8];
                }
            }
            // B fragments: 4 conflict-free lds.128
            uint4 bq[4];
            {
                const uint4* bsrc = (const uint4*)bb + s * 4 * 32 + lane;
#pragma unroll
                for (int q = 0; q < 4; q++) bq[q] = bsrc[q * 32];
            }
#pragma unroll
            for (int mi = 0; mi < 2; mi++) {
#pragma unroll
                for (int q = 0; q < 4; q++) {
                    mma_tf32(d[mi][2 * q],     a[mi], bq[q].x, bq[q].y);
                    mma_tf32(d[mi][2 * q + 1], a[mi], bq[q].z, bq[q].w);
                }
            }
        }

        if (k < KW - 1) {
            float4* dst = (float4*)(smem + ((k & 1) ? SM_B0 : SM_B1));
            dst[tid] = pf0; dst[tid + NTHR] = pf1;
            dst[tid + 2 * NTHR] = pf2; dst[tid + 3 * NTHR] = pf3;
        }
        __syncthreads();
    }

    // ---- epilogue: stage through smem (alias xs region), coalesced out ----
    float* ep = (float*)(smem + SM_XS);   // [oc][l], stride XS_STRIDE
#pragma unroll
    for (int mi = 0; mi < 2; mi++) {
#pragma unroll
        for (int f = 0; f < 8; f++) {
            int l  = ml + 16 * mi + ar;
            int oc = 8 * f + 2 * ac;
            ep[oc * XS_STRIDE + l]           = d[mi][f][0];
            ep[(oc + 1) * XS_STRIDE + l]     = d[mi][f][1];
            ep[oc * XS_STRIDE + l + 8]       = d[mi][f][2];
            ep[(oc + 1) * XS_STRIDE + l + 8] = d[mi][f][3];
        }
    }
    __syncthreads();

#pragma unroll
    for (int i = 0; i < 8; i++) {
        int oc = wid * 8 + i;
        int goc = g * OPG + oc;
        float add = g_ctx[n * C_OUT + goc] + bias[goc];
        const float4* src = (const float4*)(ep + oc * XS_STRIDE);
        float4* dst = (float4*)(out + ((size_t)(n * C_OUT + goc)) * L_LEN + l0);
#pragma unroll
        for (int it = 0; it < 2; it++) {
            float4 v = src[lane + it * 32];
            v.x += add; v.y += add; v.z += add; v.w += add;
            dst[lane + it * 32] = v;
        }
    }
}

// ---------------------------------------------------------------------------
extern "C" void kernel_launch(void* const* d_in, const int* in_sizes, int n_in,
                              void* d_out, int out_size) {
    const float* x    = (const float*)d_in[0];  // (32, 256, 4096)
    const float* c    = (const float*)d_in[1];  // (32, 128)
    const float* w    = (const float*)d_in[2];  // (256, 64, 9)
    const float* cw   = (const float*)d_in[3];  // (256, 128)
    const float* bias = (const float*)d_in[4];  // (256,)
    float* out = (float*)d_out;                 // (32, 256, 4096)

    cudaFuncSetAttribute(conv_kernel, cudaFuncAttributeMaxDynamicSharedMemorySize, SM_TOTAL);

    ctx_kernel<<<N_B, C_OUT>>>(c, cw);
    wt_kernel<<<dim3(GROUPS, KW), NTHR>>>(w);
    dim3 grid(L_LEN / L_TILE, GROUPS, N_B);     // (16, 4, 32)
    conv_kernel<<<grid, NTHR, SM_TOTAL>>>(x, bias, out);
}